// round 3
// baseline (speedup 1.0000x reference)
#include <cuda_runtime.h>
#include <cuda_bf16.h>
#include <cstdint>

// ---------------- Problem constants (fixed shapes) ----------------
#define N_  100000
#define E_  1200000
#define IN_ 128
#define H_  64
#define OUT_ 2
#define EPS_ 1e-5f

// ---------------- Device scratch (no allocations allowed) ----------------
__device__ int    g_deg[N_];
__device__ float  g_dinv[N_];
__device__ int    g_off[N_ + 1];
__device__ int    g_part[128];
__device__ int    g_cursor[N_];
__device__ float2 g_edge[E_];                 // {src as int bits, norm}
__device__ float  g_bufA[(size_t)N_ * H_];    // GEMM output (t)
__device__ float  g_bufB[(size_t)N_ * H_];    // aggregated h
__device__ float  g_A[3 * H_];                // BN scale per layer/feature
__device__ float  g_Bc[3 * H_];               // BN shift (incl. bias) per layer/feature

// ---------------- Preprocessing ----------------
__global__ void zero_deg_k() {
    int i = blockIdx.x * blockDim.x + threadIdx.x;
    if (i < N_) g_deg[i] = 0;
}

__global__ void deg_k(const int* __restrict__ ei) {
    int e = blockIdx.x * blockDim.x + threadIdx.x;
    if (e >= E_) return;
    int d = ei[E_ + e];                // col (target), int32 on the wire
    if ((unsigned)d < (unsigned)N_) atomicAdd(&g_deg[d], 1);
}

__global__ void dinv_k() {
    int i = blockIdx.x * blockDim.x + threadIdx.x;
    if (i < N_) g_dinv[i] = rsqrtf((float)(g_deg[i] + 1));   // +1 self loop
}

// BN/bias fusion: relu(h*A + B) with A = gamma*rsqrt(var+eps), B = (bias-mean)*A + beta
__global__ void bn_prep_k(const float* __restrict__ biases, const float* __restrict__ gamma,
                          const float* __restrict__ beta, const float* __restrict__ mean,
                          const float* __restrict__ var) {
    int i = threadIdx.x;   // 0..191
    if (i < 3 * H_) {
        float s = gamma[i] * rsqrtf(var[i] + EPS_);
        g_A[i]  = s;
        g_Bc[i] = (biases[i] - mean[i]) * s + beta[i];
    }
}

// ---------------- Exclusive scan over g_deg -> g_off ----------------
__global__ void scan1_k() {
    __shared__ int wsum[8];
    __shared__ int wpre[8];
    int tid  = threadIdx.x;
    int base = blockIdx.x * 1024 + tid * 4;
    int v[4]; int s = 0;
#pragma unroll
    for (int j = 0; j < 4; j++) {
        int i = base + j;
        v[j] = (i < N_) ? g_deg[i] : 0;
        s += v[j];
    }
    int lane = tid & 31, w = tid >> 5;
    int inc = s;
#pragma unroll
    for (int o = 1; o < 32; o <<= 1) {
        int t = __shfl_up_sync(0xffffffffu, inc, o);
        if (lane >= o) inc += t;
    }
    if (lane == 31) wsum[w] = inc;
    __syncthreads();
    if (tid == 0) {
        int r = 0;
#pragma unroll
        for (int k = 0; k < 8; k++) { wpre[k] = r; r += wsum[k]; }
        g_part[blockIdx.x] = r;
    }
    __syncthreads();
    int ex = wpre[w] + (inc - s);
#pragma unroll
    for (int j = 0; j < 4; j++) {
        int i = base + j;
        if (i < N_) g_off[i] = ex;
        ex += v[j];
    }
}

__global__ void scan2_k(int nb) {
    __shared__ int s[128];
    int t = threadIdx.x;
    int v = (t < nb) ? g_part[t] : 0;
    s[t] = v;
    __syncthreads();
#pragma unroll
    for (int o = 1; o < 128; o <<= 1) {
        int x = (t >= o) ? s[t - o] : 0;
        __syncthreads();
        s[t] += x;
        __syncthreads();
    }
    if (t < nb) g_part[t] = s[t] - v;   // exclusive
}

__global__ void scan3_k() {
    int i = blockIdx.x * blockDim.x + threadIdx.x;
    if (i < N_) {
        int o = g_off[i] + g_part[i >> 10];
        g_off[i]    = o;
        g_cursor[i] = o;
    }
    if (i == 0) g_off[N_] = E_;
}

// ---------------- CSR placement (counting sort by dst) ----------------
__global__ void place_k(const int* __restrict__ ei) {
    int e = blockIdx.x * blockDim.x + threadIdx.x;
    if (e >= E_) return;
    int s = ei[e];
    int d = ei[E_ + e];
    if ((unsigned)s >= (unsigned)N_ || (unsigned)d >= (unsigned)N_) return;
    float nm = g_dinv[s] * g_dinv[d];
    int p = atomicAdd(&g_cursor[d], 1);
    g_edge[p] = make_float2(__int_as_float(s), nm);
}

// ---------------- GEMM: [n,K] @ [K,64] -> g_bufA, optional fused BN+ReLU on input ----------------
template <int K, bool BN, bool EXT>
__global__ void __launch_bounds__(256) gemm_k(const float* __restrict__ Xext,
                                              const float* __restrict__ W,
                                              int abOff, int n) {
    __shared__ float Xs[64 * 65];
    __shared__ float Ws[64 * 64];
    const float* __restrict__ X = EXT ? Xext : g_bufB;
    int tid = threadIdx.x;
    int tx = tid & 15;      // 4-col group
    int ty = tid >> 4;      // 4-node group
    int node0 = blockIdx.x * 64;
    float acc[4][4] = {};

    for (int kc = 0; kc < K; kc += 64) {
        // stage W chunk [64 x 64]
#pragma unroll
        for (int m = 0; m < 16; m++) {
            int idx = tid + m * 256;
            int k = idx >> 6, j = idx & 63;
            Ws[idx] = W[(size_t)(kc + k) * 64 + j];
        }
        // stage X chunk [64 nodes x 64 k], fused BN+ReLU
#pragma unroll
        for (int m = 0; m < 16; m++) {
            int idx = tid + m * 256;
            int r = idx >> 6, c = idx & 63;
            int node = node0 + r;
            float v = (node < n) ? X[(size_t)node * K + kc + c] : 0.f;
            if (BN) v = fmaxf(fmaf(v, g_A[abOff + kc + c], g_Bc[abOff + kc + c]), 0.f);
            Xs[r * 65 + c] = v;
        }
        __syncthreads();
#pragma unroll
        for (int k = 0; k < 64; k++) {
            float4 b = *(const float4*)&Ws[k * 64 + tx * 4];
#pragma unroll
            for (int i = 0; i < 4; i++) {
                float a = Xs[(ty * 4 + i) * 65 + k];
                acc[i][0] = fmaf(a, b.x, acc[i][0]);
                acc[i][1] = fmaf(a, b.y, acc[i][1]);
                acc[i][2] = fmaf(a, b.z, acc[i][2]);
                acc[i][3] = fmaf(a, b.w, acc[i][3]);
            }
        }
        __syncthreads();
    }
#pragma unroll
    for (int i = 0; i < 4; i++) {
        int node = node0 + ty * 4 + i;
        if (node < n)
            *(float4*)&g_bufA[(size_t)node * 64 + tx * 4] =
                make_float4(acc[i][0], acc[i][1], acc[i][2], acc[i][3]);
    }
}

// ---------------- Pull-style aggregation: g_bufB[node] = dinv^2*t[node] + sum norm*t[src] ----------------
__global__ void __launch_bounds__(256) gather_k(int n) {
    int hw = (blockIdx.x * blockDim.x + threadIdx.x) >> 4;  // half-warp per node
    int l  = threadIdx.x & 15;                               // float4 slice of the 64-f row
    if (hw >= n) return;
    int node = hw;
    float d = g_dinv[node];
    float4 acc = *(const float4*)&g_bufA[(size_t)node * 64 + l * 4];
    float d2 = d * d;
    acc.x *= d2; acc.y *= d2; acc.z *= d2; acc.w *= d2;

    int s = g_off[node], e = g_off[node + 1];
    float2 ed;
    if (s < e) ed = __ldg(&g_edge[s]);
    for (int i = s; i < e; i++) {
        int src  = __float_as_int(ed.x);
        float w  = ed.y;
        if (i + 1 < e) ed = __ldg(&g_edge[i + 1]);   // prefetch next edge record
        float4 v = *(const float4*)&g_bufA[(size_t)src * 64 + l * 4];
        acc.x = fmaf(w, v.x, acc.x);
        acc.y = fmaf(w, v.y, acc.y);
        acc.z = fmaf(w, v.z, acc.z);
        acc.w = fmaf(w, v.w, acc.w);
    }
    *(float4*)&g_bufB[(size_t)node * 64 + l * 4] = acc;
}

// ---------------- Classifier: out = relu(BN2(h)) @ cls_w + cls_b ----------------
__global__ void __launch_bounds__(256) cls_k(const float* __restrict__ cw,
                                             const float* __restrict__ cb,
                                             float* __restrict__ out, int n) {
    __shared__ float ws[128];
    __shared__ float Ab[64], Bb[64];
    int tid = threadIdx.x;
    if (tid < 128) ws[tid] = cw[tid];
    if (tid < 64) { Ab[tid] = g_A[128 + tid]; Bb[tid] = g_Bc[128 + tid]; }
    __syncthreads();
    int i = blockIdx.x * blockDim.x + tid;
    if (i >= n) return;
    float a0 = __ldg(&cb[0]), a1 = __ldg(&cb[1]);
    const float4* r = (const float4*)&g_bufB[(size_t)i * 64];
#pragma unroll
    for (int q = 0; q < 16; q++) {
        float4 v = r[q];
        float vv[4] = {v.x, v.y, v.z, v.w};
#pragma unroll
        for (int c = 0; c < 4; c++) {
            int k = q * 4 + c;
            float h = fmaxf(fmaf(vv[c], Ab[k], Bb[k]), 0.f);
            a0 = fmaf(h, ws[k * 2 + 0], a0);
            a1 = fmaf(h, ws[k * 2 + 1], a1);
        }
    }
    out[(size_t)i * 2 + 0] = a0;
    out[(size_t)i * 2 + 1] = a1;
}

// ---------------- Launch ----------------
extern "C" void kernel_launch(void* const* d_in, const int* in_sizes, int n_in,
                              void* d_out, int out_size) {
    const float* x      = (const float*)d_in[0];
    const int*   ei     = (const int*)d_in[1];     // int32 on the wire (JAX x64 disabled)
    const float* w0     = (const float*)d_in[2];
    const float* w1     = (const float*)d_in[3];
    const float* w2     = (const float*)d_in[4];
    const float* biases = (const float*)d_in[5];
    const float* gamma  = (const float*)d_in[6];
    const float* beta   = (const float*)d_in[7];
    const float* rmean  = (const float*)d_in[8];
    const float* rvar   = (const float*)d_in[9];
    const float* clsw   = (const float*)d_in[10];
    const float* clsb   = (const float*)d_in[11];
    float* out = (float*)d_out;

    const int n = N_;
    const int nodeBlocks  = (n + 255) / 256;
    const int edgeBlocks  = (E_ + 255) / 256;
    const int scanBlocks  = (n + 1023) / 1024;      // 98
    const int gemmBlocks  = (n + 63) / 64;          // 1563
    const int gatherBlocks = (n * 16 + 255) / 256;  // half-warp per node

    // --- preprocessing ---
    zero_deg_k<<<nodeBlocks, 256>>>();
    deg_k<<<edgeBlocks, 256>>>(ei);
    dinv_k<<<nodeBlocks, 256>>>();
    bn_prep_k<<<1, 192>>>(biases, gamma, beta, rmean, rvar);
    scan1_k<<<scanBlocks, 256>>>();
    scan2_k<<<1, 128>>>(scanBlocks);
    scan3_k<<<nodeBlocks, 256>>>();
    place_k<<<edgeBlocks, 256>>>(ei);

    // --- layer 0: x @ w0, aggregate ---
    gemm_k<128, false, true><<<gemmBlocks, 256>>>(x, w0, 0, n);
    gather_k<<<gatherBlocks, 256>>>(n);
    // --- layer 1: relu(BN0(h)) @ w1, aggregate ---
    gemm_k<64, true, false><<<gemmBlocks, 256>>>(nullptr, w1, 0, n);
    gather_k<<<gatherBlocks, 256>>>(n);
    // --- layer 2: relu(BN1(h)) @ w2, aggregate ---
    gemm_k<64, true, false><<<gemmBlocks, 256>>>(nullptr, w2, 64, n);
    gather_k<<<gatherBlocks, 256>>>(n);
    // --- classifier with fused BN2+ReLU ---
    cls_k<<<nodeBlocks, 256>>>(clsw, clsb, out, n);
}